// round 6
// baseline (speedup 1.0000x reference)
#include <cuda_runtime.h>
#include <cstdint>

#define PB 32
#define PS 1024
#define PNODE 256
#define PDEP 64
#define PR 50
#define PL 16
#define PE 128
#define PF 320
#define NEDGE (PB * PE)     // 4096
#define NTOT (PL * NEDGE)   // 65536
#define MAXCHUNK 640
#define PREPB 64
#define MAXSLOT 288          // per (b,l): <= 128 + 3*50 padded to x4

// ---------------- scratch --------------------------------------------------
__device__ float g_child[PB * PS * PDEP];
__device__ float g_msg[NEDGE * PDEP];
__device__ float g_pmsg[PL * NEDGE * PDEP];
__device__ int   g_gsort[NTOT];
__device__ int   g_gcnt[PR];
__device__ int   g_gbase[PR + 1];
__device__ int   g_gcur[PR];
__device__ int   g_chunk_rel[MAXCHUNK];
__device__ int   g_chunk_start[MAXCHUNK];
__device__ int   g_chunk_ne[MAXCHUNK];
__device__ int   g_nchunks;
__device__ unsigned int g_ticket;
__device__ int   g_slots[PB * PL * MAXSLOT];   // (r<<7)|e, bit15 = pad
__device__ int   g_nslot[PB * PL];
__device__ int   g_hkey[NTOT];
__device__ int   g_hidx[NTOT];
__device__ unsigned int g_cbar[PB * 32];       // per-batch barrier, padded
__device__ unsigned int g_pbar;

// ---------------- f32x2 helpers -------------------------------------------
__device__ __forceinline__ void fma2(unsigned long long& acc,
                                     unsigned long long a, unsigned long long b) {
    asm("fma.rn.f32x2 %0, %1, %2, %0;" : "+l"(acc) : "l"(a), "l"(b));
}
__device__ __forceinline__ unsigned long long pack2(float x, float y) {
    unsigned long long v;
    asm("mov.b64 %0, {%1,%2};" : "=l"(v) : "r"(__float_as_uint(x)), "r"(__float_as_uint(y)));
    return v;
}
__device__ __forceinline__ void unpack2(unsigned long long v, float& x, float& y) {
    unsigned int lo, hi;
    asm("mov.b64 {%0,%1}, %2;" : "=r"(lo), "=r"(hi) : "l"(v));
    x = __uint_as_float(lo); y = __uint_as_float(hi);
}
__device__ __forceinline__ float hsum2(unsigned long long v) {
    float x, y; unpack2(v, x, y); return x + y;
}

// ---------------- launch 0: init -------------------------------------------
__global__ void k_init(const float* __restrict__ ctx, float* __restrict__ out) {
    if (blockIdx.x == 0) {
        if (threadIdx.x == 0) { g_ticket = 0; g_pbar = 0; }
        if (threadIdx.x < PR) g_gcnt[threadIdx.x] = 0;
        for (int i = threadIdx.x; i < PB * 32; i += blockDim.x) g_cbar[i] = 0;
    }
    const int64_t n_ctx = (int64_t)PB * PS * (PNODE / 4);
    const int64_t n_chd = (int64_t)PB * PS * (PDEP / 4);
    const int64_t total = n_ctx + n_chd;
    int64_t stride = (int64_t)gridDim.x * blockDim.x;
    for (int64_t i = (int64_t)blockIdx.x * blockDim.x + threadIdx.x; i < total; i += stride) {
        if (i < n_ctx) {
            int64_t row = i >> 6, d4 = i & 63;
            float4 v = ((const float4*)ctx)[i];
            *(float4*)&out[row * PF + d4 * 4] = v;
        } else {
            ((float4*)g_child)[i - n_ctx] = make_float4(0.f, 0.f, 0.f, 0.f);
        }
    }
}

// ---------------- prep barrier ---------------------------------------------
__device__ __forceinline__ void psync(int* pc) {
    __syncthreads();
    (*pc)++;
    if (threadIdx.x == 0) {
        __threadfence();
        atomicAdd(&g_pbar, 1);
        unsigned int target = (unsigned int)(PREPB * (*pc));
        while (*(volatile unsigned int*)&g_pbar < target) { }
        __threadfence();
    }
    __syncthreads();
}

// ---------------- launch 1: preprocessing ----------------------------------
__global__ void __launch_bounds__(256, 2)
k_prep(const int* __restrict__ rels, const int* __restrict__ heads) {
    int bid = blockIdx.x;
    int tid = threadIdx.x;
    int w = tid >> 5, lane = tid & 31;
    __shared__ int cnt[PR];
    __shared__ int hs2[2][128];
    __shared__ int srel[8][128];
    __shared__ int sb[PR], sch[PR];
    int pc = 0;

    // --- A1: global rel histogram (this block's 1024 edges) ---
    if (tid < PR) cnt[tid] = 0;
    __syncthreads();
    int ebase = bid * 1024;
    #pragma unroll
    for (int t = 0; t < 4; t++)
        atomicAdd(&cnt[rels[ebase + tid + t * 256]], 1);
    __syncthreads();
    if (tid < PR && cnt[tid] > 0) atomicAdd(&g_gcnt[tid], cnt[tid]);

    // --- A2: per (b,l) padded rel-quad slot lists; warp per task ---
    {
        int task = bid * 8 + w;           // 0..511
        int b = task >> 4, l = task & 15;
        #pragma unroll
        for (int t = 0; t < 4; t++)
            srel[w][lane + 32 * t] = rels[b * (PL * PE) + l * PE + lane + 32 * t];
        __syncwarp();
        int c0 = 0, c1 = 0;
        int r1 = lane + 32;
        for (int j = 0; j < PE; j++) {
            int rv = srel[w][j];
            c0 += (rv == lane);
            c1 += (rv == r1);
        }
        int p0 = (c0 + 3) & ~3;
        int p1 = (r1 < PR) ? ((c1 + 3) & ~3) : 0;
        // exclusive scans
        int s0 = p0, s1 = p1;
        #pragma unroll
        for (int o = 1; o < 32; o <<= 1) {
            int x0 = __shfl_up_sync(0xffffffffu, s0, o);
            int x1 = __shfl_up_sync(0xffffffffu, s1, o);
            if (lane >= o) { s0 += x0; s1 += x1; }
        }
        int tot0 = __shfl_sync(0xffffffffu, s0, 31);
        int tot1 = __shfl_sync(0xffffffffu, s1, 31);
        int off0 = s0 - p0;
        int off1 = tot0 + s1 - p1;
        int* dst = &g_slots[task * MAXSLOT];
        // scatter r = lane
        int o0 = off0;
        for (int j = 0; j < PE; j++)
            if (srel[w][j] == lane) dst[o0++] = (lane << 7) | j;
        while (o0 < off0 + p0) dst[o0++] = (lane << 7) | 0x8000;
        // scatter r = lane + 32
        if (p1 > 0) {
            int o1 = off1;
            for (int j = 0; j < PE; j++)
                if (srel[w][j] == r1) dst[o1++] = (r1 << 7) | j;
            while (o1 < off1 + p1) dst[o1++] = (r1 << 7) | 0x8000;
        }
        if (lane == 31) g_nslot[task] = tot0 + tot1;
    }

    // --- A3: head rank-sort; 8 (l,b) tasks per block ---
    #pragma unroll
    for (int t = 0; t < 4; t++) {
        int task = bid * 8 + t * 2 + (tid >> 7);
        int l = task >> 5, b = task & 31;
        int e = tid & 127;
        int h = heads[b * (PL * PE) + l * PE + e];
        hs2[tid >> 7][e] = h;
        __syncthreads();
        int rank = 0;
        #pragma unroll 8
        for (int o = 0; o < PE; o++) {
            int ho = hs2[tid >> 7][o];
            rank += (ho < h) || (ho == h && o < e);
        }
        int base = l * NEDGE + b * PE;
        g_hkey[base + rank] = h;
        g_hidx[base + rank] = e;
        __syncthreads();
    }

    psync(&pc);

    // --- B: prefix + chunk worklist (block 0) ---
    if (bid == 0) {
        if (tid == 0) {
            int s = 0, nc = 0;
            for (int r = 0; r < PR; r++) {
                sb[r] = s;
                sch[r] = nc;
                int c = g_gcnt[r];
                s += c;
                nc += (c + 127) >> 7;
            }
            g_gbase[PR] = s;
            g_nchunks = nc;
        }
        __syncthreads();
        if (tid < PR) {
            int b0 = sb[tid];
            g_gbase[tid] = b0;
            g_gcur[tid] = b0;
            int c = g_gcnt[tid];
            int nc0 = sch[tid];
            for (int o = 0, k = 0; o < c; o += 128, k++) {
                g_chunk_rel[nc0 + k] = tid;
                g_chunk_start[nc0 + k] = b0 + o;
                g_chunk_ne[nc0 + k] = min(128, c - o);
            }
        }
    }

    psync(&pc);

    // --- C: global scatter with range reservation ---
    __shared__ int rbase[PR], rcur[PR];
    if (tid < PR) rcur[tid] = 0;
    __syncthreads();
    if (tid < PR) rbase[tid] = (cnt[tid] > 0) ? atomicAdd(&g_gcur[tid], cnt[tid]) : 0;
    __syncthreads();
    #pragma unroll
    for (int t = 0; t < 4; t++) {
        int idx = ebase + tid + t * 256;
        int r = rels[idx];
        int pos = rbase[r] + atomicAdd(&rcur[r], 1);
        int b = idx >> 11, l = (idx >> 7) & 15, e = idx & 127;
        g_gsort[pos] = (l << 12) | (b << 7) | e;
    }
}

// ---------------- launch 2: pmsg (unchanged ticket-queue core) -------------
#define PM_STRIDE 260
#define PM_SMEM ((64 * PM_STRIDE + 128 * PM_STRIDE) * (int)sizeof(float))

__global__ void __launch_bounds__(256, 1)
k_pmsg(const float* __restrict__ ctx, const float* __restrict__ W,
       const int* __restrict__ tails) {
    extern __shared__ float sm[];
    float* Ws = sm;
    float* Fs = sm + 64 * PM_STRIDE;
    __shared__ int seid[128];
    __shared__ int stail[128];
    __shared__ int s_chunk;
    int tid = threadIdx.x;

    while (true) {
        if (tid == 0) s_chunk = atomicAdd(&g_ticket, 1);
        __syncthreads();
        int c = s_chunk;
        if (c >= g_nchunks) break;
        int r = g_chunk_rel[c];
        int start = g_chunk_start[c];
        int ne = g_chunk_ne[c];

        if (tid < 128) {
            int v = (tid < ne) ? g_gsort[start + tid] : -1;
            seid[tid] = v;
            int tnode = 0;
            if (v >= 0) {
                int b = (v >> 7) & 31, l = v >> 12, e = v & 127;
                tnode = b * PS + tails[b * (PL * PE) + l * PE + e];
            }
            stail[tid] = tnode;
        }
        const float* Wg = W + (int64_t)r * PDEP * PF;
        #pragma unroll
        for (int t = 0; t < 16; t++) {
            int idx = tid + t * 256;
            int k = idx >> 6, cc = idx & 63;
            *(float4*)&Ws[k * PM_STRIDE + cc * 4] = *(const float4*)&Wg[k * PF + cc * 4];
        }
        __syncthreads();

        #pragma unroll
        for (int t = 0; t < 32; t++) {
            int idx = tid + t * 256;
            int row = idx >> 6, cc = idx & 63;
            float4 v = make_float4(0.f, 0.f, 0.f, 0.f);
            if (seid[row] >= 0)
                v = *(const float4*)&ctx[(int64_t)stail[row] * PNODE + cc * 4];
            *(float4*)&Fs[row * PM_STRIDE + cc * 4] = v;
        }
        __syncthreads();

        int eg = tid & 31;
        int kg = tid >> 5;
        unsigned long long acc[4][8];
        #pragma unroll
        for (int i = 0; i < 4; i++)
            #pragma unroll
            for (int j = 0; j < 8; j++) acc[i][j] = 0ull;

        #pragma unroll 4
        for (int d = 0; d < PNODE; d += 4) {
            ulonglong2 w[8];
            #pragma unroll
            for (int j = 0; j < 8; j++)
                w[j] = *(const ulonglong2*)&Ws[(kg + 8 * j) * PM_STRIDE + d];
            #pragma unroll
            for (int i = 0; i < 4; i++) {
                ulonglong2 f = *(const ulonglong2*)&Fs[(eg + 32 * i) * PM_STRIDE + d];
                #pragma unroll
                for (int j = 0; j < 8; j++) {
                    fma2(acc[i][j], f.x, w[j].x);
                    fma2(acc[i][j], f.y, w[j].y);
                }
            }
        }

        #pragma unroll
        for (int i = 0; i < 4; i++) {
            int v = seid[eg + 32 * i];
            if (v >= 0) {
                int l = v >> 12, edge = v & 4095;
                float* dst = &g_pmsg[((int64_t)l * NEDGE + edge) * PDEP];
                #pragma unroll
                for (int j = 0; j < 8; j++)
                    dst[kg + 8 * j] = hsum2(acc[i][j]);
            }
        }
        __syncthreads();
    }
}

// ---------------- launch 3: per-(batch, k-quarter) chain -------------------
// 128 blocks, 256 threads, 1/SM. W2 k-slice (50x16x64 fp32, quad layout)
// staged ONCE in smem. One 4-arrival per-batch barrier per layer.
#define CH_W_FLOATS (PR * 16 * PDEP)                 // 51200 -> 204800 B
#define CH_CB_STRIDE 68
#define CH_SMEM ((CH_W_FLOATS + 64 * CH_CB_STRIDE) * (int)sizeof(float))

__global__ void __launch_bounds__(256, 1)
k_chain(const float* __restrict__ W, const int* __restrict__ tails,
        float* __restrict__ out) {
    extern __shared__ float sm[];
    float* Ws = sm;                        // quads: [(r*32+d2)*8 + k2]*4
    float* Cb = sm + CH_W_FLOATS;          // [64][68] child rows
    __shared__ int s_slot[64];
    __shared__ int s_tn[64];
    __shared__ int s_hk[128];
    __shared__ int s_hx[128];

    int bid = blockIdx.x;
    int b = bid >> 2, kq = bid & 3;
    int tid = threadIdx.x;
    int wid = tid >> 5, lane = tid & 31;
    int kl2 = tid & 7;                     // k-pair 0..7
    int srow = tid >> 3;                   // slot row 0..31

    // stage W2 k-slice into quad layout:
    // quad(r,d2,k2) = (W[2k2][2d2], W[2k2+1][2d2], W[2k2][2d2+1], W[2k2+1][2d2+1])
    for (int idx = tid; idx < PR * 16 * 16; idx += 256) {
        int r = idx >> 8, rem = idx & 255;
        int k = rem >> 4, d4 = rem & 15;   // k row 0..15, d4 group
        float4 v = *(const float4*)&W[((int64_t)r * PDEP + kq * 16 + k) * PF + PNODE + d4 * 4];
        float vv[4] = {v.x, v.y, v.z, v.w};
        #pragma unroll
        for (int i = 0; i < 4; i++) {
            int d = d4 * 4 + i;
            Ws[((r * 32 + (d >> 1)) * 8 + (k >> 1)) * 4 + (k & 1) + 2 * (d & 1)] = vv[i];
        }
    }

    unsigned int* bar = &g_cbar[b * 32];
    float* childb = &g_child[b * PS * PDEP];

    for (int l = 0; l < PL; l++) {
        // stage head segment data
        if (tid < 128) {
            s_hk[tid] = g_hkey[l * NEDGE + b * PE + tid];
            s_hx[tid] = g_hidx[l * NEDGE + b * PE + tid];
        }
        __syncthreads();

        if (l > 0) {
            int nslot = g_nslot[b * PL + l];
            const int* slots = &g_slots[(b * PL + l) * MAXSLOT];
            for (int cs = 0; cs < nslot; cs += 64) {
                __syncthreads();
                if (tid < 64) {
                    int sv = (cs + tid < nslot) ? slots[cs + tid] : -1;
                    s_slot[tid] = sv;
                    int tn = 0;
                    if (sv >= 0 && !(sv & 0x8000))
                        tn = tails[b * (PL * PE) + l * PE + (sv & 127)];
                    s_tn[tid] = tn;
                }
                __syncthreads();
                // gather child rows (one burst)
                #pragma unroll
                for (int t = 0; t < 4; t++) {
                    int idx = tid + t * 256;     // 1024 float4 = 64 rows x 16
                    int row = idx >> 4, c4 = idx & 15;
                    float4 v = make_float4(0.f, 0.f, 0.f, 0.f);
                    int sv = s_slot[row];
                    if (sv >= 0 && !(sv & 0x8000))
                        v = __ldcg((const float4*)&childb[s_tn[row] * PDEP + c4 * 4]);
                    *(float4*)&Cb[row * CH_CB_STRIDE + c4 * 4] = v;
                }
                __syncthreads();

                // compute: 2 passes x 32 slots, thread = (slot, k-pair)
                #pragma unroll
                for (int pass = 0; pass < 2; pass++) {
                    int sg = pass * 32 + srow;
                    int sv = s_slot[sg];
                    int r = (sv < 0) ? 0 : ((sv >> 7) & 63);
                    bool real = (sv >= 0) && !(sv & 0x8000);
                    // prefetch pmsg pair
                    float2 pm = make_float2(0.f, 0.f);
                    if (real) {
                        int e = sv & 127;
                        pm = __ldcg((const float2*)&g_pmsg[
                            ((int64_t)l * NEDGE + b * PE + e) * PDEP + kq * 16 + 2 * kl2]);
                    }
                    unsigned long long acc = 0ull;
                    const float* wp = &Ws[(r * 32) * 32 + kl2 * 4];
                    const float* cp = &Cb[sg * CH_CB_STRIDE];
                    #pragma unroll 8
                    for (int d2 = 0; d2 < 32; d2++) {
                        ulonglong2 wq = *(const ulonglong2*)&wp[d2 * 32];
                        float2 cd = *(const float2*)&cp[d2 * 2];
                        fma2(acc, wq.x, pack2(cd.x, cd.x));
                        fma2(acc, wq.y, pack2(cd.y, cd.y));
                    }
                    if (real) {
                        int e = sv & 127;
                        float a0, a1;
                        unpack2(acc, a0, a1);
                        float2 o = make_float2(a0 + pm.x, a1 + pm.y);
                        __stcg((float2*)&g_msg[(b * PE + e) * PDEP + kq * 16 + 2 * kl2], o);
                    }
                }
            }
            __syncthreads();
        }

        // phase 2: segment average of this k-slice (block-local)
        {
            const float* msrc = (l == 0) ? g_pmsg : g_msg;
            int64_t mbase = (l == 0) ? ((int64_t)0 * NEDGE) : 0;   // pmsg layer0 at offset 0
            for (int i = 0; i < 16; i++) {
                int p = wid * 16 + i;
                int h = s_hk[p];
                if (p > 0 && s_hk[p - 1] == h) continue;
                int len = 1;
                while (p + len < PE && s_hk[p + len] == h) len++;
                float s = 0.f;
                if (lane < 16) {
                    for (int j = 0; j < len; j++) {
                        int e = s_hx[p + j];
                        s += __ldcg(&msrc[(mbase + b * PE + e) * PDEP + kq * 16 + lane]);
                    }
                    __stcg(&childb[h * PDEP + kq * 16 + lane], s * (1.f / (float)len));
                }
            }
        }

        // per-batch barrier (skip after last layer: out-write is k-slice-local)
        if (l + 1 < PL) {
            __syncthreads();
            if (tid == 0) {
                __threadfence();
                atomicAdd(bar, 1);
                unsigned int target = (unsigned int)(4 * (l + 1));
                while (*(volatile unsigned int*)bar < target) { }
                __threadfence();
            }
            __syncthreads();
        }
    }

    // out[:, b, :, 256 + kq*16 .. +16]  (own writes only; no barrier needed)
    __syncthreads();
    #pragma unroll
    for (int t = 0; t < 16; t++) {
        int idx = tid + t * 256;           // 4096 float4
        int s = idx >> 2, q = idx & 3;
        float4 v;
        v.x = __ldcg(&childb[s * PDEP + kq * 16 + q * 4 + 0]);
        v.y = __ldcg(&childb[s * PDEP + kq * 16 + q * 4 + 1]);
        v.z = __ldcg(&childb[s * PDEP + kq * 16 + q * 4 + 2]);
        v.w = __ldcg(&childb[s * PDEP + kq * 16 + q * 4 + 3]);
        *(float4*)&out[((int64_t)(b * PS + s)) * PF + PNODE + kq * 16 + q * 4] = v;
    }
}

// ---------------------------------------------------------------------------
extern "C" void kernel_launch(void* const* d_in, const int* in_sizes, int n_in,
                              void* d_out, int out_size) {
    const float* ctx   = (const float*)d_in[0];
    const float* W     = (const float*)d_in[1];
    const int*   heads = (const int*)d_in[2];
    const int*   tails = (const int*)d_in[3];
    const int*   rels  = (const int*)d_in[4];
    float*       out   = (float*)d_out;

    cudaFuncSetAttribute(k_pmsg, cudaFuncAttributeMaxDynamicSharedMemorySize, PM_SMEM);
    cudaFuncSetAttribute(k_chain, cudaFuncAttributeMaxDynamicSharedMemorySize, CH_SMEM);

    k_init<<<2048, 256>>>(ctx, out);                 // launch 0
    k_prep<<<PREPB, 256>>>(rels, heads);             // launch 1
    k_pmsg<<<148, 256, PM_SMEM>>>(ctx, W, tails);    // launch 2
    k_chain<<<PB * 4, 256, CH_SMEM>>>(W, tails, out); // launch 3
}

// round 7
// speedup vs baseline: 1.5080x; 1.5080x over previous
#include <cuda_runtime.h>
#include <cstdint>

#define PB 32
#define PS 1024
#define PNODE 256
#define PDEP 64
#define PR 50
#define PL 16
#define PE 128
#define PF 320
#define NEDGE (PB * PE)     // 4096
#define NTOT (PL * NEDGE)   // 65536
#define MAXCHUNK 640
#define PREPB 64
#define MAXSLOT 288

// chain partitioning: 16 groups x 8 rel-octant blocks, 2 batches per group
#define CGRP 8
#define NGRP2 16
#define CH_BLOCKS (NGRP2 * CGRP)   // 128

// ---------------- scratch --------------------------------------------------
__device__ float g_child[PB * PS * PDEP];
__device__ float g_msg[NEDGE * PDEP];
__device__ float g_pmsg[PL * NEDGE * PDEP];
__device__ int   g_gsort[NTOT];
__device__ int   g_gcnt[PR];
__device__ int   g_gbase[PR + 1];
__device__ int   g_gcur[PR];
__device__ int   g_chunk_rel[MAXCHUNK];
__device__ int   g_chunk_start[MAXCHUNK];
__device__ int   g_chunk_ne[MAXCHUNK];
__device__ int   g_nchunks;
__device__ unsigned int g_ticket;
__device__ int   g_slots[PB * PL * MAXSLOT];     // (r<<7)|e, bit15 = pad
__device__ int   g_slotoff[PB * PL * (PR + 1)];  // padded exclusive offsets
__device__ int   g_nslot[PB * PL];
__device__ int   g_hkey[NTOT];
__device__ int   g_hidx[NTOT];
__device__ unsigned int g_cbar[PB * 32];
__device__ unsigned int g_pbar;

__device__ __constant__ int R0T[9] = {0, 7, 14, 20, 26, 32, 38, 44, 50};

// ---------------- f32x2 helpers -------------------------------------------
__device__ __forceinline__ void fma2(unsigned long long& acc,
                                     unsigned long long a, unsigned long long b) {
    asm("fma.rn.f32x2 %0, %1, %2, %0;" : "+l"(acc) : "l"(a), "l"(b));
}
__device__ __forceinline__ float hsum2(unsigned long long v) {
    unsigned int lo, hi;
    asm("mov.b64 {%0,%1}, %2;" : "=r"(lo), "=r"(hi) : "l"(v));
    return __uint_as_float(lo) + __uint_as_float(hi);
}

// ---------------- launch 0: init -------------------------------------------
__global__ void k_init(const float* __restrict__ ctx, float* __restrict__ out) {
    if (blockIdx.x == 0) {
        if (threadIdx.x == 0) { g_ticket = 0; g_pbar = 0; }
        if (threadIdx.x < PR) g_gcnt[threadIdx.x] = 0;
        for (int i = threadIdx.x; i < PB * 32; i += blockDim.x) g_cbar[i] = 0;
    }
    const int64_t n_ctx = (int64_t)PB * PS * (PNODE / 4);
    const int64_t n_chd = (int64_t)PB * PS * (PDEP / 4);
    const int64_t total = n_ctx + n_chd;
    int64_t stride = (int64_t)gridDim.x * blockDim.x;
    for (int64_t i = (int64_t)blockIdx.x * blockDim.x + threadIdx.x; i < total; i += stride) {
        if (i < n_ctx) {
            int64_t row = i >> 6, d4 = i & 63;
            float4 v = ((const float4*)ctx)[i];
            *(float4*)&out[row * PF + d4 * 4] = v;
        } else {
            ((float4*)g_child)[i - n_ctx] = make_float4(0.f, 0.f, 0.f, 0.f);
        }
    }
}

// ---------------- prep barrier ---------------------------------------------
__device__ __forceinline__ void psync(int* pc) {
    __syncthreads();
    (*pc)++;
    if (threadIdx.x == 0) {
        __threadfence();
        atomicAdd(&g_pbar, 1);
        unsigned int target = (unsigned int)(PREPB * (*pc));
        while (*(volatile unsigned int*)&g_pbar < target) { }
        __threadfence();
    }
    __syncthreads();
}

// ---------------- launch 1: preprocessing ----------------------------------
__global__ void __launch_bounds__(256, 2)
k_prep(const int* __restrict__ rels, const int* __restrict__ heads) {
    int bid = blockIdx.x;
    int tid = threadIdx.x;
    int w = tid >> 5, lane = tid & 31;
    __shared__ int cnt[PR];
    __shared__ int hs2[2][128];
    __shared__ int srel[8][128];
    __shared__ int sb[PR], sch[PR];
    int pc = 0;

    // --- A1: global rel histogram ---
    if (tid < PR) cnt[tid] = 0;
    __syncthreads();
    int ebase = bid * 1024;
    #pragma unroll
    for (int t = 0; t < 4; t++)
        atomicAdd(&cnt[rels[ebase + tid + t * 256]], 1);
    __syncthreads();
    if (tid < PR && cnt[tid] > 0) atomicAdd(&g_gcnt[tid], cnt[tid]);

    // --- A2: per (b,l) padded rel-quad slot lists + offset table ---
    {
        int task = bid * 8 + w;           // 0..511 = b*PL + l
        int b = task >> 4, l = task & 15;
        #pragma unroll
        for (int t = 0; t < 4; t++)
            srel[w][lane + 32 * t] = rels[b * (PL * PE) + l * PE + lane + 32 * t];
        __syncwarp();
        int c0 = 0, c1 = 0;
        int r1 = lane + 32;
        for (int j = 0; j < PE; j++) {
            int rv = srel[w][j];
            c0 += (rv == lane);
            c1 += (rv == r1);
        }
        int p0 = (c0 + 3) & ~3;
        int p1 = (r1 < PR) ? ((c1 + 3) & ~3) : 0;
        int s0 = p0, s1 = p1;
        #pragma unroll
        for (int o = 1; o < 32; o <<= 1) {
            int x0 = __shfl_up_sync(0xffffffffu, s0, o);
            int x1 = __shfl_up_sync(0xffffffffu, s1, o);
            if (lane >= o) { s0 += x0; s1 += x1; }
        }
        int tot0 = __shfl_sync(0xffffffffu, s0, 31);
        int tot1 = __shfl_sync(0xffffffffu, s1, 31);
        int off0 = s0 - p0;
        int off1 = tot0 + s1 - p1;
        int* dst = &g_slots[task * MAXSLOT];
        int* doff = &g_slotoff[task * (PR + 1)];
        doff[lane] = off0;
        if (r1 < PR) doff[r1] = off1;
        if (lane == 31) doff[PR] = tot0 + tot1;
        int o0 = off0;
        for (int j = 0; j < PE; j++)
            if (srel[w][j] == lane) dst[o0++] = (lane << 7) | j;
        while (o0 < off0 + p0) dst[o0++] = (lane << 7) | 0x8000;
        if (p1 > 0) {
            int o1 = off1;
            for (int j = 0; j < PE; j++)
                if (srel[w][j] == r1) dst[o1++] = (r1 << 7) | j;
            while (o1 < off1 + p1) dst[o1++] = (r1 << 7) | 0x8000;
        }
        if (lane == 31) g_nslot[task] = tot0 + tot1;
    }

    // --- A3: head rank-sort ---
    #pragma unroll
    for (int t = 0; t < 4; t++) {
        int task = bid * 8 + t * 2 + (tid >> 7);
        int l = task >> 5, b = task & 31;
        int e = tid & 127;
        int h = heads[b * (PL * PE) + l * PE + e];
        hs2[tid >> 7][e] = h;
        __syncthreads();
        int rank = 0;
        #pragma unroll 8
        for (int o = 0; o < PE; o++) {
            int ho = hs2[tid >> 7][o];
            rank += (ho < h) || (ho == h && o < e);
        }
        int base = l * NEDGE + b * PE;
        g_hkey[base + rank] = h;
        g_hidx[base + rank] = e;
        __syncthreads();
    }

    psync(&pc);

    // --- B: prefix + chunk worklist (block 0) ---
    if (bid == 0) {
        if (tid == 0) {
            int s = 0, nc = 0;
            for (int r = 0; r < PR; r++) {
                sb[r] = s;
                sch[r] = nc;
                int c = g_gcnt[r];
                s += c;
                nc += (c + 127) >> 7;
            }
            g_gbase[PR] = s;
            g_nchunks = nc;
        }
        __syncthreads();
        if (tid < PR) {
            int b0 = sb[tid];
            g_gbase[tid] = b0;
            g_gcur[tid] = b0;
            int c = g_gcnt[tid];
            int nc0 = sch[tid];
            for (int o = 0, k = 0; o < c; o += 128, k++) {
                g_chunk_rel[nc0 + k] = tid;
                g_chunk_start[nc0 + k] = b0 + o;
                g_chunk_ne[nc0 + k] = min(128, c - o);
            }
        }
    }

    psync(&pc);

    // --- C: global scatter with range reservation ---
    __shared__ int rbase[PR], rcur[PR];
    if (tid < PR) rcur[tid] = 0;
    __syncthreads();
    if (tid < PR) rbase[tid] = (cnt[tid] > 0) ? atomicAdd(&g_gcur[tid], cnt[tid]) : 0;
    __syncthreads();
    #pragma unroll
    for (int t = 0; t < 4; t++) {
        int idx = ebase + tid + t * 256;
        int r = rels[idx];
        int pos = rbase[r] + atomicAdd(&rcur[r], 1);
        int b = idx >> 11, l = (idx >> 7) & 15, e = idx & 127;
        g_gsort[pos] = (l << 12) | (b << 7) | e;
    }
}

// ---------------- launch 2: pmsg (ticket-queue, unchanged core) ------------
#define PM_STRIDE 260
#define PM_SMEM ((64 * PM_STRIDE + 128 * PM_STRIDE) * (int)sizeof(float))

__global__ void __launch_bounds__(256, 1)
k_pmsg(const float* __restrict__ ctx, const float* __restrict__ W,
       const int* __restrict__ tails) {
    extern __shared__ float sm[];
    float* Ws = sm;
    float* Fs = sm + 64 * PM_STRIDE;
    __shared__ int seid[128];
    __shared__ int stail[128];
    __shared__ int s_chunk;
    int tid = threadIdx.x;

    while (true) {
        if (tid == 0) s_chunk = atomicAdd(&g_ticket, 1);
        __syncthreads();
        int c = s_chunk;
        if (c >= g_nchunks) break;
        int r = g_chunk_rel[c];
        int start = g_chunk_start[c];
        int ne = g_chunk_ne[c];

        if (tid < 128) {
            int v = (tid < ne) ? g_gsort[start + tid] : -1;
            seid[tid] = v;
            int tnode = 0;
            if (v >= 0) {
                int b = (v >> 7) & 31, l = v >> 12, e = v & 127;
                tnode = b * PS + tails[b * (PL * PE) + l * PE + e];
            }
            stail[tid] = tnode;
        }
        const float* Wg = W + (int64_t)r * PDEP * PF;
        #pragma unroll
        for (int t = 0; t < 16; t++) {
            int idx = tid + t * 256;
            int k = idx >> 6, cc = idx & 63;
            *(float4*)&Ws[k * PM_STRIDE + cc * 4] = *(const float4*)&Wg[k * PF + cc * 4];
        }
        __syncthreads();

        #pragma unroll
        for (int t = 0; t < 32; t++) {
            int idx = tid + t * 256;
            int row = idx >> 6, cc = idx & 63;
            float4 v = make_float4(0.f, 0.f, 0.f, 0.f);
            if (seid[row] >= 0)
                v = *(const float4*)&ctx[(int64_t)stail[row] * PNODE + cc * 4];
            *(float4*)&Fs[row * PM_STRIDE + cc * 4] = v;
        }
        __syncthreads();

        int eg = tid & 31;
        int kg = tid >> 5;
        unsigned long long acc[4][8];
        #pragma unroll
        for (int i = 0; i < 4; i++)
            #pragma unroll
            for (int j = 0; j < 8; j++) acc[i][j] = 0ull;

        #pragma unroll 4
        for (int d = 0; d < PNODE; d += 4) {
            ulonglong2 w[8];
            #pragma unroll
            for (int j = 0; j < 8; j++)
                w[j] = *(const ulonglong2*)&Ws[(kg + 8 * j) * PM_STRIDE + d];
            #pragma unroll
            for (int i = 0; i < 4; i++) {
                ulonglong2 f = *(const ulonglong2*)&Fs[(eg + 32 * i) * PM_STRIDE + d];
                #pragma unroll
                for (int j = 0; j < 8; j++) {
                    fma2(acc[i][j], f.x, w[j].x);
                    fma2(acc[i][j], f.y, w[j].y);
                }
            }
        }

        #pragma unroll
        for (int i = 0; i < 4; i++) {
            int v = seid[eg + 32 * i];
            if (v >= 0) {
                int l = v >> 12, edge = v & 4095;
                float* dst = &g_pmsg[((int64_t)l * NEDGE + edge) * PDEP];
                #pragma unroll
                for (int j = 0; j < 8; j++)
                    dst[kg + 8 * j] = hsum2(acc[i][j]);
            }
        }
        __syncthreads();
    }
}

// ---------------- launch 3: chain: (2-batch group) x (rel octant) ----------
#define WSTR 68
#define CH_NR_MAX 7
#define CH_W_FLOATS (CH_NR_MAX * 64 * WSTR)      // 30464
#define CH_SMEM ((CH_W_FLOATS + 64 * WSTR) * (int)sizeof(float))   // 139264

__global__ void __launch_bounds__(256, 1)
k_chain(const float* __restrict__ W, const int* __restrict__ tails,
        float* __restrict__ out) {
    extern __shared__ float sm[];
    float* Ws = sm;                          // [NR][64][WSTR]
    float* Cb = sm + CH_W_FLOATS;            // [64][WSTR]
    __shared__ int s_slot[320];
    __shared__ int s_tn[320];
    __shared__ int s_hk[128];
    __shared__ int s_hx[128];

    int bid = blockIdx.x;
    int g = bid >> 3, i = bid & 7;
    int R0 = R0T[i], R1 = R0T[i + 1];
    int NR = R1 - R0;
    int b0 = g * 2, b1 = g * 2 + 1;
    int pb = g * 2 + (i >> 2);               // phase-2 batch
    int kq = i & 3;                          // phase-2 k-quarter
    int tid = threadIdx.x;
    int q = tid >> 4, kg = tid & 15;

    // stage W2 slice for rels [R0, R1)
    for (int idx = tid; idx < NR * 64 * 16; idx += 256) {
        int kr = idx >> 4, d4 = idx & 15;
        int rl = kr >> 6, k = kr & 63;
        float4 v = *(const float4*)&W[((int64_t)(R0 + rl) * PDEP + k) * PF + PNODE + d4 * 4];
        *(float4*)&Ws[kr * WSTR + d4 * 4] = v;
    }
    // stage hkey/hidx for layer 0
    if (tid < 128) {
        s_hk[tid] = __ldg(&g_hkey[pb * PE + tid]);
        s_hx[tid] = __ldg(&g_hidx[pb * PE + tid]);
    }
    __syncthreads();

    unsigned int* bar = &g_cbar[g * 32];
    int calls = 0;
    int len_cur = 0;

    for (int l = 0; l < PL; l++) {
        // ================= phase 1 (l > 0) =================
        if (l > 0) {
            for (int t0 = 0; t0 < len_cur; t0 += 64) {
                __syncthreads();
                // gather child rows for this tile
                #pragma unroll
                for (int t = 0; t < 4; t++) {
                    int idx = tid + t * 256;
                    int row = idx >> 4, c4 = idx & 15;
                    int sidx = t0 + row;
                    int sv = (sidx < len_cur) ? s_slot[sidx] : -1;
                    float4 v = make_float4(0.f, 0.f, 0.f, 0.f);
                    if (sv >= 0 && !(sv & 0x8000))
                        v = __ldcg((const float4*)&g_child[s_tn[sidx] * PDEP + c4 * 4]);
                    *(float4*)&Cb[row * WSTR + c4 * 4] = v;
                }
                __syncthreads();
                // compute: thread = (quad q, k-group kg)
                int sbase = t0 + 4 * q;
                int sv0 = (sbase < len_cur) ? s_slot[sbase] : -1;
                if (sv0 >= 0) {
                    int r = (sv0 >> 7) & 63;
                    int rl = r - R0;
                    int sv[4];
                    #pragma unroll
                    for (int ii = 0; ii < 4; ii++) sv[ii] = s_slot[sbase + ii];
                    float pm[4][4];
                    #pragma unroll
                    for (int ii = 0; ii < 4; ii++) {
                        #pragma unroll
                        for (int j = 0; j < 4; j++) pm[ii][j] = 0.f;
                        if (!(sv[ii] & 0x8000)) {
                            int e = sv[ii] & 127;
                            int bb = g * 2 + ((sv[ii] >> 16) & 1);
                            const float* p = &g_pmsg[((int64_t)l * NEDGE + bb * PE + e) * PDEP];
                            #pragma unroll
                            for (int j = 0; j < 4; j++)
                                pm[ii][j] = __ldcg(&p[kg + 16 * j]);
                        }
                    }
                    unsigned long long acc[4][4];
                    #pragma unroll
                    for (int ii = 0; ii < 4; ii++)
                        #pragma unroll
                        for (int j = 0; j < 4; j++) acc[ii][j] = 0ull;
                    const float* wp = &Ws[(rl * 64 + kg) * WSTR];
                    const float* cp = &Cb[(4 * (sbase - t0) / 4) * 0 + ( (sbase - t0) ) * WSTR];
                    // note: sbase - t0 = 4*q → rows 4q..4q+3
                    #pragma unroll 4
                    for (int d = 0; d < PDEP; d += 4) {
                        ulonglong2 w0 = *(const ulonglong2*)&wp[d];
                        ulonglong2 w1 = *(const ulonglong2*)&wp[16 * WSTR + d];
                        ulonglong2 w2 = *(const ulonglong2*)&wp[32 * WSTR + d];
                        ulonglong2 w3 = *(const ulonglong2*)&wp[48 * WSTR + d];
                        #pragma unroll
                        for (int ii = 0; ii < 4; ii++) {
                            ulonglong2 f = *(const ulonglong2*)&cp[ii * WSTR + d];
                            fma2(acc[ii][0], f.x, w0.x); fma2(acc[ii][0], f.y, w0.y);
                            fma2(acc[ii][1], f.x, w1.x); fma2(acc[ii][1], f.y, w1.y);
                            fma2(acc[ii][2], f.x, w2.x); fma2(acc[ii][2], f.y, w2.y);
                            fma2(acc[ii][3], f.x, w3.x); fma2(acc[ii][3], f.y, w3.y);
                        }
                    }
                    #pragma unroll
                    for (int ii = 0; ii < 4; ii++) {
                        if (!(sv[ii] & 0x8000)) {
                            int e = sv[ii] & 127;
                            int bb = g * 2 + ((sv[ii] >> 16) & 1);
                            float* dst = &g_msg[(bb * PE + e) * PDEP];
                            #pragma unroll
                            for (int j = 0; j < 4; j++)
                                __stcg(&dst[kg + 16 * j], hsum2(acc[ii][j]) + pm[ii][j]);
                        }
                    }
                }
            }
            // fence + arrive A
            __syncthreads();
            calls++;
            if (tid == 0) { __threadfence(); atomicAdd(bar, 1); }
        }

        // ---- gap A: prefetch next layer's static data into registers ----
        int pf_sv0 = -1, pf_sv1 = -1, pf_tn0 = 0, pf_tn1 = 0;
        int pf_hk = 0, pf_hx = 0, pf_len = 0;
        if (l + 1 < PL) {
            const int* so0 = &g_slotoff[(b0 * PL + l + 1) * (PR + 1)];
            const int* so1 = &g_slotoff[(b1 * PL + l + 1) * (PR + 1)];
            int a0 = __ldg(&so0[R0]), z0 = __ldg(&so0[R1]);
            int a1 = __ldg(&so1[R0]), z1 = __ldg(&so1[R1]);
            int L0 = z0 - a0, L1 = z1 - a1;
            pf_len = L0 + L1;
            // slot 0: index tid
            if (tid < pf_len) {
                int sv;
                if (tid < L0) sv = __ldg(&g_slots[(b0 * PL + l + 1) * MAXSLOT + a0 + tid]);
                else sv = __ldg(&g_slots[(b1 * PL + l + 1) * MAXSLOT + a1 + tid - L0]) | (1 << 16);
                pf_sv0 = sv;
                if (!(sv & 0x8000)) {
                    int bb = g * 2 + ((sv >> 16) & 1);
                    pf_tn0 = bb * PS + __ldg(&tails[bb * (PL * PE) + (l + 1) * PE + (sv & 127)]);
                }
            }
            // slot 1: index tid + 256
            int idx2 = tid + 256;
            if (idx2 < pf_len) {
                int sv;
                if (idx2 < L0) sv = __ldg(&g_slots[(b0 * PL + l + 1) * MAXSLOT + a0 + idx2]);
                else sv = __ldg(&g_slots[(b1 * PL + l + 1) * MAXSLOT + a1 + idx2 - L0]) | (1 << 16);
                pf_sv1 = sv;
                if (!(sv & 0x8000)) {
                    int bb = g * 2 + ((sv >> 16) & 1);
                    pf_tn1 = bb * PS + __ldg(&tails[bb * (PL * PE) + (l + 1) * PE + (sv & 127)]);
                }
            }
            if (tid < 128) {
                pf_hk = __ldg(&g_hkey[(l + 1) * NEDGE + pb * PE + tid]);
                pf_hx = __ldg(&g_hidx[(l + 1) * NEDGE + pb * PE + tid]);
            }
        }

        // ---- wait A ----
        if (l > 0) {
            if (tid == 0) {
                unsigned int target = (unsigned int)(CGRP * calls);
                while (*(volatile unsigned int*)bar < target) { }
                __threadfence();
            }
            __syncthreads();
        }

        // ================= phase 2: segment average =================
        {
            const float* msrc = (l == 0) ? g_pmsg : g_msg;
            int wid = tid >> 5, lane = tid & 31;
            int sub = lane >> 4, kl = lane & 15;
            #pragma unroll
            for (int it = 0; it < 8; it++) {
                int p = wid * 16 + it * 2 + sub;
                int h = s_hk[p];
                if (p > 0 && s_hk[p - 1] == h) continue;
                int len = 1;
                while (p + len < PE && s_hk[p + len] == h) len++;
                float s = 0.f;
                for (int j = 0; j < len; j++) {
                    int e = s_hx[p + j];
                    s += __ldcg(&msrc[(pb * PE + e) * PDEP + kq * 16 + kl]);
                }
                __stcg(&g_child[(pb * PS + h) * PDEP + kq * 16 + kl], s * (1.f / (float)len));
            }
        }

        if (l + 1 < PL) {
            // fence + arrive B
            __syncthreads();
            calls++;
            if (tid == 0) { __threadfence(); atomicAdd(bar, 1); }
            // gap B: commit prefetched data to smem
            if (tid < 320) { s_slot[tid] = (tid < pf_len) ? pf_sv0 : -1; s_tn[tid] = pf_tn0; }
            int idx2 = tid + 256;
            if (idx2 < 320) { s_slot[idx2] = (idx2 < pf_len) ? pf_sv1 : -1; s_tn[idx2] = pf_tn1; }
            if (tid < 128) { s_hk[tid] = pf_hk; s_hx[tid] = pf_hx; }
            len_cur = pf_len;
            // wait B
            if (tid == 0) {
                unsigned int target = (unsigned int)(CGRP * calls);
                while (*(volatile unsigned int*)bar < target) { }
                __threadfence();
            }
            __syncthreads();
        }
    }

    // ---- out write: own (batch, k-quarter) slice; no inter-block dep ----
    __syncthreads();
    #pragma unroll
    for (int t = 0; t < 16; t++) {
        int idx = tid + t * 256;              // 4096 float4
        int srow = idx >> 2, c4 = idx & 3;
        const float* c = &g_child[(pb * PS + srow) * PDEP + kq * 16 + c4 * 4];
        float4 v;
        v.x = __ldcg(&c[0]); v.y = __ldcg(&c[1]);
        v.z = __ldcg(&c[2]); v.w = __ldcg(&c[3]);
        *(float4*)&out[((int64_t)(pb * PS + srow)) * PF + PNODE + kq * 16 + c4 * 4] = v;
    }
}

// ---------------------------------------------------------------------------
extern "C" void kernel_launch(void* const* d_in, const int* in_sizes, int n_in,
                              void* d_out, int out_size) {
    const float* ctx   = (const float*)d_in[0];
    const float* W     = (const float*)d_in[1];
    const int*   heads = (const int*)d_in[2];
    const int*   tails = (const int*)d_in[3];
    const int*   rels  = (const int*)d_in[4];
    float*       out   = (float*)d_out;

    cudaFuncSetAttribute(k_pmsg, cudaFuncAttributeMaxDynamicSharedMemorySize, PM_SMEM);
    cudaFuncSetAttribute(k_chain, cudaFuncAttributeMaxDynamicSharedMemorySize, CH_SMEM);

    k_init<<<2048, 256>>>(ctx, out);                  // launch 0
    k_prep<<<PREPB, 256>>>(rels, heads);              // launch 1
    k_pmsg<<<148, 256, PM_SMEM>>>(ctx, W, tails);     // launch 2
    k_chain<<<CH_BLOCKS, 256, CH_SMEM>>>(W, tails, out); // launch 3
}

// round 8
// speedup vs baseline: 1.6127x; 1.0695x over previous
#include <cuda_runtime.h>
#include <cstdint>

#define PB 32
#define PS 1024
#define PNODE 256
#define PDEP 64
#define PR 50
#define PL 16
#define PE 128
#define PF 320
#define NEDGE (PB * PE)     // 4096
#define NTOT (PL * NEDGE)   // 65536
#define MAXCHUNK 640
#define PREPB 64
#define MAXSLOT 288

// chain partitioning: 16 groups x 8 rel-octant blocks, 2 batches per group
#define CGRP 8
#define NGRP2 16
#define CH_BLOCKS (NGRP2 * CGRP)   // 128

// ---------------- scratch --------------------------------------------------
__device__ float g_child[PB * PS * PDEP];
__device__ float g_msg[NEDGE * PDEP];
__device__ float g_pmsg[PL * NEDGE * PDEP];
__device__ int   g_gsort[NTOT];
__device__ int   g_gcnt[PR];
__device__ int   g_gbase[PR + 1];
__device__ int   g_gcur[PR];
__device__ int   g_chunk_rel[MAXCHUNK];
__device__ int   g_chunk_start[MAXCHUNK];
__device__ int   g_chunk_ne[MAXCHUNK];
__device__ int   g_nchunks;
__device__ unsigned int g_ticket;
__device__ int   g_slots[PB * PL * MAXSLOT];     // (r<<7)|e, bit15 = pad
__device__ int   g_slotoff[PB * PL * (PR + 1)];  // padded exclusive offsets
__device__ int   g_nslot[PB * PL];
__device__ int   g_hkey[NTOT];
__device__ int   g_hidx[NTOT];
__device__ unsigned int g_cbar[PB * 32];
__device__ unsigned int g_pbar;

__device__ __constant__ int R0T[9] = {0, 7, 14, 20, 26, 32, 38, 44, 50};

// ---------------- f32x2 helpers -------------------------------------------
__device__ __forceinline__ void fma2(unsigned long long& acc,
                                     unsigned long long a, unsigned long long b) {
    asm("fma.rn.f32x2 %0, %1, %2, %0;" : "+l"(acc) : "l"(a), "l"(b));
}
__device__ __forceinline__ float hsum2(unsigned long long v) {
    unsigned int lo, hi;
    asm("mov.b64 {%0,%1}, %2;" : "=r"(lo), "=r"(hi) : "l"(v));
    return __uint_as_float(lo) + __uint_as_float(hi);
}

// ---------------- launch 0: init -------------------------------------------
__global__ void k_init(const float* __restrict__ ctx, float* __restrict__ out) {
    if (blockIdx.x == 0) {
        if (threadIdx.x == 0) { g_ticket = 0; g_pbar = 0; }
        if (threadIdx.x < PR) g_gcnt[threadIdx.x] = 0;
        for (int i = threadIdx.x; i < PB * 32; i += blockDim.x) g_cbar[i] = 0;
    }
    const int64_t n_ctx = (int64_t)PB * PS * (PNODE / 4);
    const int64_t n_chd = (int64_t)PB * PS * (PDEP / 4);
    const int64_t total = n_ctx + n_chd;
    int64_t stride = (int64_t)gridDim.x * blockDim.x;
    for (int64_t i = (int64_t)blockIdx.x * blockDim.x + threadIdx.x; i < total; i += stride) {
        if (i < n_ctx) {
            int64_t row = i >> 6, d4 = i & 63;
            float4 v = ((const float4*)ctx)[i];
            *(float4*)&out[row * PF + d4 * 4] = v;
        } else {
            ((float4*)g_child)[i - n_ctx] = make_float4(0.f, 0.f, 0.f, 0.f);
        }
    }
}

// ---------------- prep barrier ---------------------------------------------
__device__ __forceinline__ void psync(int* pc) {
    __syncthreads();
    (*pc)++;
    if (threadIdx.x == 0) {
        __threadfence();
        atomicAdd(&g_pbar, 1);
        unsigned int target = (unsigned int)(PREPB * (*pc));
        while (*(volatile unsigned int*)&g_pbar < target) { }
        __threadfence();
    }
    __syncthreads();
}

// ---------------- launch 1: preprocessing ----------------------------------
__global__ void __launch_bounds__(256, 2)
k_prep(const int* __restrict__ rels, const int* __restrict__ heads) {
    int bid = blockIdx.x;
    int tid = threadIdx.x;
    int w = tid >> 5, lane = tid & 31;
    __shared__ int cnt[PR];
    __shared__ int hs2[2][128];
    __shared__ int srel[8][128];
    __shared__ int sb[PR], sch[PR];
    int pc = 0;

    // --- A1: global rel histogram ---
    if (tid < PR) cnt[tid] = 0;
    __syncthreads();
    int ebase = bid * 1024;
    #pragma unroll
    for (int t = 0; t < 4; t++)
        atomicAdd(&cnt[rels[ebase + tid + t * 256]], 1);
    __syncthreads();
    if (tid < PR && cnt[tid] > 0) atomicAdd(&g_gcnt[tid], cnt[tid]);

    // --- A2: per (b,l) padded rel-quad slot lists + offset table ---
    {
        int task = bid * 8 + w;           // 0..511 = b*PL + l
        int b = task >> 4, l = task & 15;
        #pragma unroll
        for (int t = 0; t < 4; t++)
            srel[w][lane + 32 * t] = rels[b * (PL * PE) + l * PE + lane + 32 * t];
        __syncwarp();
        int c0 = 0, c1 = 0;
        int r1 = lane + 32;
        for (int j = 0; j < PE; j++) {
            int rv = srel[w][j];
            c0 += (rv == lane);
            c1 += (rv == r1);
        }
        int p0 = (c0 + 3) & ~3;
        int p1 = (r1 < PR) ? ((c1 + 3) & ~3) : 0;
        int s0 = p0, s1 = p1;
        #pragma unroll
        for (int o = 1; o < 32; o <<= 1) {
            int x0 = __shfl_up_sync(0xffffffffu, s0, o);
            int x1 = __shfl_up_sync(0xffffffffu, s1, o);
            if (lane >= o) { s0 += x0; s1 += x1; }
        }
        int tot0 = __shfl_sync(0xffffffffu, s0, 31);
        int tot1 = __shfl_sync(0xffffffffu, s1, 31);
        int off0 = s0 - p0;
        int off1 = tot0 + s1 - p1;
        int* dst = &g_slots[task * MAXSLOT];
        int* doff = &g_slotoff[task * (PR + 1)];
        doff[lane] = off0;
        if (r1 < PR) doff[r1] = off1;
        if (lane == 31) doff[PR] = tot0 + tot1;
        int o0 = off0;
        for (int j = 0; j < PE; j++)
            if (srel[w][j] == lane) dst[o0++] = (lane << 7) | j;
        while (o0 < off0 + p0) dst[o0++] = (lane << 7) | 0x8000;
        if (p1 > 0) {
            int o1 = off1;
            for (int j = 0; j < PE; j++)
                if (srel[w][j] == r1) dst[o1++] = (r1 << 7) | j;
            while (o1 < off1 + p1) dst[o1++] = (r1 << 7) | 0x8000;
        }
        if (lane == 31) g_nslot[task] = tot0 + tot1;
    }

    // --- A3: head rank-sort ---
    #pragma unroll
    for (int t = 0; t < 4; t++) {
        int task = bid * 8 + t * 2 + (tid >> 7);
        int l = task >> 5, b = task & 31;
        int e = tid & 127;
        int h = heads[b * (PL * PE) + l * PE + e];
        hs2[tid >> 7][e] = h;
        __syncthreads();
        int rank = 0;
        #pragma unroll 8
        for (int o = 0; o < PE; o++) {
            int ho = hs2[tid >> 7][o];
            rank += (ho < h) || (ho == h && o < e);
        }
        int base = l * NEDGE + b * PE;
        g_hkey[base + rank] = h;
        g_hidx[base + rank] = e;
        __syncthreads();
    }

    psync(&pc);

    // --- B: prefix + chunk worklist (block 0) ---
    if (bid == 0) {
        if (tid == 0) {
            int s = 0, nc = 0;
            for (int r = 0; r < PR; r++) {
                sb[r] = s;
                sch[r] = nc;
                int c = g_gcnt[r];
                s += c;
                nc += (c + 127) >> 7;
            }
            g_gbase[PR] = s;
            g_nchunks = nc;
        }
        __syncthreads();
        if (tid < PR) {
            int b0 = sb[tid];
            g_gbase[tid] = b0;
            g_gcur[tid] = b0;
            int c = g_gcnt[tid];
            int nc0 = sch[tid];
            for (int o = 0, k = 0; o < c; o += 128, k++) {
                g_chunk_rel[nc0 + k] = tid;
                g_chunk_start[nc0 + k] = b0 + o;
                g_chunk_ne[nc0 + k] = min(128, c - o);
            }
        }
    }

    psync(&pc);

    // --- C: global scatter with range reservation ---
    __shared__ int rbase[PR], rcur[PR];
    if (tid < PR) rcur[tid] = 0;
    __syncthreads();
    if (tid < PR) rbase[tid] = (cnt[tid] > 0) ? atomicAdd(&g_gcur[tid], cnt[tid]) : 0;
    __syncthreads();
    #pragma unroll
    for (int t = 0; t < 4; t++) {
        int idx = ebase + tid + t * 256;
        int r = rels[idx];
        int pos = rbase[r] + atomicAdd(&rcur[r], 1);
        int b = idx >> 11, l = (idx >> 7) & 15, e = idx & 127;
        g_gsort[pos] = (l << 12) | (b << 7) | e;
    }
}

// ---------------- launch 2: pmsg (ticket-queue, unchanged core) ------------
#define PM_STRIDE 260
#define PM_SMEM ((64 * PM_STRIDE + 128 * PM_STRIDE) * (int)sizeof(float))

__global__ void __launch_bounds__(256, 1)
k_pmsg(const float* __restrict__ ctx, const float* __restrict__ W,
       const int* __restrict__ tails) {
    extern __shared__ float sm[];
    float* Ws = sm;
    float* Fs = sm + 64 * PM_STRIDE;
    __shared__ int seid[128];
    __shared__ int stail[128];
    __shared__ int s_chunk;
    int tid = threadIdx.x;

    while (true) {
        if (tid == 0) s_chunk = atomicAdd(&g_ticket, 1);
        __syncthreads();
        int c = s_chunk;
        if (c >= g_nchunks) break;
        int r = g_chunk_rel[c];
        int start = g_chunk_start[c];
        int ne = g_chunk_ne[c];

        if (tid < 128) {
            int v = (tid < ne) ? g_gsort[start + tid] : -1;
            seid[tid] = v;
            int tnode = 0;
            if (v >= 0) {
                int b = (v >> 7) & 31, l = v >> 12, e = v & 127;
                tnode = b * PS + tails[b * (PL * PE) + l * PE + e];
            }
            stail[tid] = tnode;
        }
        const float* Wg = W + (int64_t)r * PDEP * PF;
        #pragma unroll
        for (int t = 0; t < 16; t++) {
            int idx = tid + t * 256;
            int k = idx >> 6, cc = idx & 63;
            *(float4*)&Ws[k * PM_STRIDE + cc * 4] = *(const float4*)&Wg[k * PF + cc * 4];
        }
        __syncthreads();

        #pragma unroll
        for (int t = 0; t < 32; t++) {
            int idx = tid + t * 256;
            int row = idx >> 6, cc = idx & 63;
            float4 v = make_float4(0.f, 0.f, 0.f, 0.f);
            if (seid[row] >= 0)
                v = *(const float4*)&ctx[(int64_t)stail[row] * PNODE + cc * 4];
            *(float4*)&Fs[row * PM_STRIDE + cc * 4] = v;
        }
        __syncthreads();

        int eg = tid & 31;
        int kg = tid >> 5;
        unsigned long long acc[4][8];
        #pragma unroll
        for (int i = 0; i < 4; i++)
            #pragma unroll
            for (int j = 0; j < 8; j++) acc[i][j] = 0ull;

        #pragma unroll 4
        for (int d = 0; d < PNODE; d += 4) {
            ulonglong2 w[8];
            #pragma unroll
            for (int j = 0; j < 8; j++)
                w[j] = *(const ulonglong2*)&Ws[(kg + 8 * j) * PM_STRIDE + d];
            #pragma unroll
            for (int i = 0; i < 4; i++) {
                ulonglong2 f = *(const ulonglong2*)&Fs[(eg + 32 * i) * PM_STRIDE + d];
                #pragma unroll
                for (int j = 0; j < 8; j++) {
                    fma2(acc[i][j], f.x, w[j].x);
                    fma2(acc[i][j], f.y, w[j].y);
                }
            }
        }

        #pragma unroll
        for (int i = 0; i < 4; i++) {
            int v = seid[eg + 32 * i];
            if (v >= 0) {
                int l = v >> 12, edge = v & 4095;
                float* dst = &g_pmsg[((int64_t)l * NEDGE + edge) * PDEP];
                #pragma unroll
                for (int j = 0; j < 8; j++)
                    dst[kg + 8 * j] = hsum2(acc[i][j]);
            }
        }
        __syncthreads();
    }
}

// ---------------- launch 3: chain: (2-batch group) x (rel octant) ----------
#define WSTR 68
#define CH_NR_MAX 7
#define CH_W_FLOATS (CH_NR_MAX * 64 * WSTR)      // 30464
#define CH_SMEM ((CH_W_FLOATS + 64 * WSTR) * (int)sizeof(float))   // 139264

__global__ void __launch_bounds__(256, 1)
k_chain(const float* __restrict__ W, const int* __restrict__ tails,
        float* __restrict__ out) {
    extern __shared__ float sm[];
    float* Ws = sm;                          // [NR][64][WSTR]
    float* Cb = sm + CH_W_FLOATS;            // [64][WSTR]; reused as msg stage
    __shared__ int s_slot[320];
    __shared__ int s_tn[320];
    __shared__ int s_hk[128];
    __shared__ int s_hx[128];

    int bid = blockIdx.x;
    int g = bid >> 3, i = bid & 7;
    int R0 = R0T[i], R1 = R0T[i + 1];
    int NR = R1 - R0;
    int b0 = g * 2, b1 = g * 2 + 1;
    int pb = g * 2 + (i >> 2);               // phase-2 batch
    int kq = i & 3;                          // phase-2 k-quarter
    int tid = threadIdx.x;
    int q = tid >> 4, kg = tid & 15;

    // stage W2 slice for rels [R0, R1)
    for (int idx = tid; idx < NR * 64 * 16; idx += 256) {
        int kr = idx >> 4, d4 = idx & 15;
        int rl = kr >> 6, k = kr & 63;
        float4 v = *(const float4*)&W[((int64_t)(R0 + rl) * PDEP + k) * PF + PNODE + d4 * 4];
        *(float4*)&Ws[kr * WSTR + d4 * 4] = v;
    }
    // stage hkey/hidx for layer 0
    if (tid < 128) {
        s_hk[tid] = __ldg(&g_hkey[pb * PE + tid]);
        s_hx[tid] = __ldg(&g_hidx[pb * PE + tid]);
    }
    __syncthreads();

    unsigned int* bar = &g_cbar[g * 32];
    int calls = 0;
    int len_cur = 0;

    for (int l = 0; l < PL; l++) {
        // ================= phase 1 (l > 0) =================
        if (l > 0) {
            for (int t0 = 0; t0 < len_cur; t0 += 64) {
                __syncthreads();
                // gather child rows for this tile
                #pragma unroll
                for (int t = 0; t < 4; t++) {
                    int idx = tid + t * 256;
                    int row = idx >> 4, c4 = idx & 15;
                    int sidx = t0 + row;
                    int sv = (sidx < len_cur) ? s_slot[sidx] : -1;
                    float4 v = make_float4(0.f, 0.f, 0.f, 0.f);
                    if (sv >= 0 && !(sv & 0x8000))
                        v = __ldcg((const float4*)&g_child[s_tn[sidx] * PDEP + c4 * 4]);
                    *(float4*)&Cb[row * WSTR + c4 * 4] = v;
                }
                __syncthreads();
                // compute: thread = (quad q, k-group kg)
                int sbase = t0 + 4 * q;
                int sv0 = (sbase < len_cur) ? s_slot[sbase] : -1;
                if (sv0 >= 0) {
                    int r = (sv0 >> 7) & 63;
                    int rl = r - R0;
                    int sv[4];
                    #pragma unroll
                    for (int ii = 0; ii < 4; ii++) sv[ii] = s_slot[sbase + ii];
                    float pm[4][4];
                    #pragma unroll
                    for (int ii = 0; ii < 4; ii++) {
                        #pragma unroll
                        for (int j = 0; j < 4; j++) pm[ii][j] = 0.f;
                        if (!(sv[ii] & 0x8000)) {
                            int e = sv[ii] & 127;
                            int bb = g * 2 + ((sv[ii] >> 16) & 1);
                            const float* p = &g_pmsg[((int64_t)l * NEDGE + bb * PE + e) * PDEP];
                            #pragma unroll
                            for (int j = 0; j < 4; j++)
                                pm[ii][j] = __ldcg(&p[kg + 16 * j]);
                        }
                    }
                    unsigned long long acc[4][4];
                    #pragma unroll
                    for (int ii = 0; ii < 4; ii++)
                        #pragma unroll
                        for (int j = 0; j < 4; j++) acc[ii][j] = 0ull;
                    const float* wp = &Ws[(rl * 64 + kg) * WSTR];
                    const float* cp = &Cb[4 * q * WSTR];
                    #pragma unroll 4
                    for (int d = 0; d < PDEP; d += 4) {
                        ulonglong2 w0 = *(const ulonglong2*)&wp[d];
                        ulonglong2 w1 = *(const ulonglong2*)&wp[16 * WSTR + d];
                        ulonglong2 w2 = *(const ulonglong2*)&wp[32 * WSTR + d];
                        ulonglong2 w3 = *(const ulonglong2*)&wp[48 * WSTR + d];
                        #pragma unroll
                        for (int ii = 0; ii < 4; ii++) {
                            ulonglong2 f = *(const ulonglong2*)&cp[ii * WSTR + d];
                            fma2(acc[ii][0], f.x, w0.x); fma2(acc[ii][0], f.y, w0.y);
                            fma2(acc[ii][1], f.x, w1.x); fma2(acc[ii][1], f.y, w1.y);
                            fma2(acc[ii][2], f.x, w2.x); fma2(acc[ii][2], f.y, w2.y);
                            fma2(acc[ii][3], f.x, w3.x); fma2(acc[ii][3], f.y, w3.y);
                        }
                    }
                    #pragma unroll
                    for (int ii = 0; ii < 4; ii++) {
                        if (!(sv[ii] & 0x8000)) {
                            int e = sv[ii] & 127;
                            int bb = g * 2 + ((sv[ii] >> 16) & 1);
                            float* dst = &g_msg[(bb * PE + e) * PDEP];
                            #pragma unroll
                            for (int j = 0; j < 4; j++)
                                __stcg(&dst[kg + 16 * j], hsum2(acc[ii][j]) + pm[ii][j]);
                        }
                    }
                }
            }
            // fence + arrive A
            __syncthreads();
            calls++;
            if (tid == 0) { __threadfence(); atomicAdd(bar, 1); }
        }

        // ---- gap A: prefetch next layer's static data into registers ----
        int pf_sv0 = -1, pf_sv1 = -1, pf_tn0 = 0, pf_tn1 = 0;
        int pf_hk = 0, pf_hx = 0, pf_len = 0;
        if (l + 1 < PL) {
            const int* so0 = &g_slotoff[(b0 * PL + l + 1) * (PR + 1)];
            const int* so1 = &g_slotoff[(b1 * PL + l + 1) * (PR + 1)];
            int a0 = __ldg(&so0[R0]), z0 = __ldg(&so0[R1]);
            int a1 = __ldg(&so1[R0]), z1 = __ldg(&so1[R1]);
            int L0 = z0 - a0, L1 = z1 - a1;
            pf_len = L0 + L1;
            if (tid < pf_len) {
                int sv;
                if (tid < L0) sv = __ldg(&g_slots[(b0 * PL + l + 1) * MAXSLOT + a0 + tid]);
                else sv = __ldg(&g_slots[(b1 * PL + l + 1) * MAXSLOT + a1 + tid - L0]) | (1 << 16);
                pf_sv0 = sv;
                if (!(sv & 0x8000)) {
                    int bb = g * 2 + ((sv >> 16) & 1);
                    pf_tn0 = bb * PS + __ldg(&tails[bb * (PL * PE) + (l + 1) * PE + (sv & 127)]);
                }
            }
            int idx2 = tid + 256;
            if (idx2 < pf_len) {
                int sv;
                if (idx2 < L0) sv = __ldg(&g_slots[(b0 * PL + l + 1) * MAXSLOT + a0 + idx2]);
                else sv = __ldg(&g_slots[(b1 * PL + l + 1) * MAXSLOT + a1 + idx2 - L0]) | (1 << 16);
                pf_sv1 = sv;
                if (!(sv & 0x8000)) {
                    int bb = g * 2 + ((sv >> 16) & 1);
                    pf_tn1 = bb * PS + __ldg(&tails[bb * (PL * PE) + (l + 1) * PE + (sv & 127)]);
                }
            }
            if (tid < 128) {
                pf_hk = __ldg(&g_hkey[(l + 1) * NEDGE + pb * PE + tid]);
                pf_hx = __ldg(&g_hidx[(l + 1) * NEDGE + pb * PE + tid]);
            }
        }

        // ---- wait A ----
        if (l > 0) {
            if (tid == 0) {
                unsigned int target = (unsigned int)(CGRP * calls);
                while (*(volatile unsigned int*)bar < target) { }
                __threadfence();
            }
            __syncthreads();
        }

        // ================= phase 2: smem-staged segment average =============
        {
            const float* msrc = (l == 0) ? g_pmsg : g_msg;
            float* Ms = Cb;                   // 2048 floats, reuse gather buffer
            #pragma unroll
            for (int t = 0; t < 2; t++) {
                int idx = tid + t * 256;      // 512 float4
                int e = idx >> 2, c4 = idx & 3;
                float4 v = __ldcg((const float4*)&msrc[
                    ((int64_t)(pb * PE + e)) * PDEP + kq * 16 + c4 * 4]);
                *(float4*)&Ms[e * 16 + c4 * 4] = v;
            }
            __syncthreads();
            int wid = tid >> 5, lane = tid & 31;
            int sub = lane >> 4, kl = lane & 15;
            #pragma unroll
            for (int it = 0; it < 8; it++) {
                int p = wid * 16 + it * 2 + sub;
                int h = s_hk[p];
                if (p > 0 && s_hk[p - 1] == h) continue;
                int len = 1;
                while (p + len < PE && s_hk[p + len] == h) len++;
                float s = 0.f;
                for (int j = 0; j < len; j++)
                    s += Ms[s_hx[p + j] * 16 + kl];
                __stcg(&g_child[(pb * PS + h) * PDEP + kq * 16 + kl],
                       s * (1.f / (float)len));
            }
        }

        if (l + 1 < PL) {
            // fence + arrive B
            __syncthreads();
            calls++;
            if (tid == 0) { __threadfence(); atomicAdd(bar, 1); }
            // gap B: commit prefetched data to smem
            if (tid < 320) { s_slot[tid] = (tid < pf_len) ? pf_sv0 : -1; s_tn[tid] = pf_tn0; }
            int idx2 = tid + 256;
            if (idx2 < 320) { s_slot[idx2] = (idx2 < pf_len) ? pf_sv1 : -1; s_tn[idx2] = pf_tn1; }
            if (tid < 128) { s_hk[tid] = pf_hk; s_hx[tid] = pf_hx; }
            len_cur = pf_len;
            // wait B
            if (tid == 0) {
                unsigned int target = (unsigned int)(CGRP * calls);
                while (*(volatile unsigned int*)bar < target) { }
                __threadfence();
            }
            __syncthreads();
        }
    }

    // ---- out write: own (batch, k-quarter) slice; no inter-block dep ----
    __syncthreads();
    #pragma unroll
    for (int t = 0; t < 16; t++) {
        int idx = tid + t * 256;              // 4096 float4
        int srow = idx >> 2, c4 = idx & 3;
        const float* c = &g_child[(pb * PS + srow) * PDEP + kq * 16 + c4 * 4];
        float4 v;
        v.x = __ldcg(&c[0]); v.y = __ldcg(&c[1]);
        v.z = __ldcg(&c[2]); v.w = __ldcg(&c[3]);
        *(float4*)&out[((int64_t)(pb * PS + srow)) * PF + PNODE + kq * 16 + c4 * 4] = v;
    }
}

// ---------------------------------------------------------------------------
extern "C" void kernel_launch(void* const* d_in, const int* in_sizes, int n_in,
                              void* d_out, int out_size) {
    const float* ctx   = (const float*)d_in[0];
    const float* W     = (const float*)d_in[1];
    const int*   heads = (const int*)d_in[2];
    const int*   tails = (const int*)d_in[3];
    const int*   rels  = (const int*)d_in[4];
    float*       out   = (float*)d_out;

    cudaFuncSetAttribute(k_pmsg, cudaFuncAttributeMaxDynamicSharedMemorySize, PM_SMEM);
    cudaFuncSetAttribute(k_chain, cudaFuncAttributeMaxDynamicSharedMemorySize, CH_SMEM);

    k_init<<<2048, 256>>>(ctx, out);                  // launch 0
    k_prep<<<PREPB, 256>>>(rels, heads);              // launch 1
    k_pmsg<<<148, 256, PM_SMEM>>>(ctx, W, tails);     // launch 2
    k_chain<<<CH_BLOCKS, 256, CH_SMEM>>>(W, tails, out); // launch 3
}